// round 9
// baseline (speedup 1.0000x reference)
#include <cuda_runtime.h>
#include <math.h>
#include <stdint.h>

#define T 4096
#define D 1024
#define H 16
#define DH 64
#define L 32

#define VS2 68   // VT row stride in words: 68 % 32 == 4 -> conflict-free stores+ldsm

// Scratch (allocation-free rule: __device__ globals)
__device__ float g_Qh[H * T * DH];
__device__ float g_Kh[H * T * DH];
__device__ float g_Vh[H * T * DH];
__device__ float g_Vals[T * D];

__device__ __forceinline__ uint32_t f2tf(float f) {
    uint32_t r;
    asm("cvt.rna.tf32.f32 %0, %1;" : "=r"(r) : "f"(f));
    return r;
}

__device__ __forceinline__ float ex2(float f) {
    float r;
    asm("ex2.approx.f32 %0, %1;" : "=f"(r) : "f"(f));
    return r;
}

__device__ __forceinline__ void mma_tf32(float c[4], uint32_t a0, uint32_t a1,
                                         uint32_t a2, uint32_t a3,
                                         uint32_t b0, uint32_t b1) {
    asm volatile(
        "mma.sync.aligned.m16n8k8.row.col.f32.tf32.tf32.f32 "
        "{%0,%1,%2,%3}, {%4,%5,%6,%7}, {%8,%9}, {%0,%1,%2,%3};\n"
        : "+f"(c[0]), "+f"(c[1]), "+f"(c[2]), "+f"(c[3])
        : "r"(a0), "r"(a1), "r"(a2), "r"(a3), "r"(b0), "r"(b1));
}

__device__ __forceinline__ void ldsm4(uint32_t& d0, uint32_t& d1, uint32_t& d2,
                                      uint32_t& d3, uint32_t saddr) {
    asm volatile(
        "ldmatrix.sync.aligned.m8n8.x4.shared.b16 {%0,%1,%2,%3}, [%4];"
        : "=r"(d0), "=r"(d1), "=r"(d2), "=r"(d3)
        : "r"(saddr));
}

// ---------------------------------------------------------------------------
// Projection GEMM (tf32 mma.sync + ldmatrix).
// out = X[M,K] @ W[N,K]^T.  Block tile 128x128, BK=32. 256 threads = 8 warps.
// mode 0: row-major out [T,1024].
// mode 1: RoPE + head-major out [H][T][DH]; bx covers heads 2bx, 2bx+1.
// ---------------------------------------------------------------------------
__device__ __forceinline__ void proj_body(
    const float* __restrict__ X, const float* __restrict__ W,
    const float* __restrict__ freqs, float* __restrict__ out, int mode,
    int bx, int by)
{
    __shared__ uint32_t As[128 * 32];   // 16 KB
    __shared__ uint32_t Bs[128 * 32];   // 16 KB

    const int tid = threadIdx.x;
    const int lane = tid & 31;
    const int w = tid >> 5;
    const int gid = lane >> 2;
    const int tig = lane & 3;
    const int wm = w >> 1;
    const int wn = w & 1;

    const int lsub = lane >> 3;
    const int lr = lane & 7;
    const int khA = lsub >> 1;
    const int khB = lsub & 1;

    const uint32_t as_s = (uint32_t)__cvta_generic_to_shared(As);
    const uint32_t bs_s = (uint32_t)__cvta_generic_to_shared(Bs);

    uint32_t aA[2];
#pragma unroll
    for (int mt = 0; mt < 2; mt++) {
        int rowA = wm * 32 + mt * 16 + lr + ((lsub & 1) << 3);
        aA[mt] = as_s + rowA * 128;
    }
    uint32_t bB[4];
#pragma unroll
    for (int np = 0; np < 4; np++) {
        int n = wn * 64 + np * 16 + lr + ((lsub >> 1) << 3);
        bB[np] = bs_s + n * 128;
    }

    float acc[2][8][4];
#pragma unroll
    for (int mt = 0; mt < 2; mt++)
#pragma unroll
        for (int nt = 0; nt < 8; nt++)
#pragma unroll
            for (int r = 0; r < 4; r++) acc[mt][nt][r] = 0.f;

    int rows_[4], kgs_[4];
#pragma unroll
    for (int i = 0; i < 4; i++) {
        int f = tid + i * 256;
        rows_[i] = f >> 3;
        kgs_[i] = f & 7;
    }

    float4 ra[4], rb[4];
#pragma unroll
    for (int i = 0; i < 4; i++) {
        ra[i] = *(const float4*)(X + (size_t)(by * 128 + rows_[i]) * D + kgs_[i] * 4);
        rb[i] = *(const float4*)(W + (size_t)(bx * 128 + rows_[i]) * D + kgs_[i] * 4);
    }

    for (int kk = 0; kk < 32; kk++) {
        __syncthreads();
#pragma unroll
        for (int i = 0; i < 4; i++) {
            uint4 ua = make_uint4(f2tf(ra[i].x), f2tf(ra[i].y), f2tf(ra[i].z), f2tf(ra[i].w));
            *(uint4*)&As[rows_[i] * 32 + ((kgs_[i] ^ (rows_[i] & 7)) << 2)] = ua;
            uint4 ub = make_uint4(f2tf(rb[i].x), f2tf(rb[i].y), f2tf(rb[i].z), f2tf(rb[i].w));
            *(uint4*)&Bs[rows_[i] * 32 + ((kgs_[i] ^ (rows_[i] & 7)) << 2)] = ub;
        }
        __syncthreads();

        if (kk < 31) {
            int k0 = (kk + 1) * 32;
#pragma unroll
            for (int i = 0; i < 4; i++) {
                ra[i] = *(const float4*)(X + (size_t)(by * 128 + rows_[i]) * D + k0 + kgs_[i] * 4);
                rb[i] = *(const float4*)(W + (size_t)(bx * 128 + rows_[i]) * D + k0 + kgs_[i] * 4);
            }
        }

#pragma unroll
        for (int ks = 0; ks < 4; ks++) {
            uint32_t a[2][4];
#pragma unroll
            for (int mt = 0; mt < 2; mt++)
                ldsm4(a[mt][0], a[mt][1], a[mt][2], a[mt][3],
                      aA[mt] + (((2 * ks + khA) ^ lr) << 4));
#pragma unroll
            for (int np = 0; np < 4; np++) {
                uint32_t b00, b01, b10, b11;
                ldsm4(b00, b01, b10, b11, bB[np] + (((2 * ks + khB) ^ lr) << 4));
#pragma unroll
                for (int mt = 0; mt < 2; mt++) {
                    mma_tf32(acc[mt][2 * np], a[mt][0], a[mt][1], a[mt][2], a[mt][3], b00, b01);
                    mma_tf32(acc[mt][2 * np + 1], a[mt][0], a[mt][1], a[mt][2], a[mt][3], b10, b11);
                }
            }
        }
    }

    if (mode == 0) {
#pragma unroll
        for (int mt = 0; mt < 2; mt++) {
#pragma unroll
            for (int rh = 0; rh < 2; rh++) {
                int t = by * 128 + wm * 32 + mt * 16 + gid + rh * 8;
#pragma unroll
                for (int nt = 0; nt < 8; nt++) {
                    int col = bx * 128 + wn * 64 + nt * 8 + tig * 2;
                    float2 v = make_float2(acc[mt][nt][rh * 2], acc[mt][nt][rh * 2 + 1]);
                    *(float2*)(out + (size_t)t * D + col) = v;
                }
            }
        }
    } else {
        const int h = bx * 2 + wn;
#pragma unroll
        for (int mt = 0; mt < 2; mt++) {
#pragma unroll
            for (int rh = 0; rh < 2; rh++) {
                int t = by * 128 + wm * 32 + mt * 16 + gid + rh * 8;
                float* orow = out + (size_t)h * T * DH + (size_t)t * DH;
#pragma unroll
                for (int nt = 0; nt < 8; nt++) {
                    int c = nt * 8 + tig * 2;
                    if (nt < 4) {
                        float2 f2 = *(const float2*)(freqs + (size_t)t * L + c);
                        float x0 = acc[mt][nt][rh * 2];
                        float x1 = acc[mt][nt][rh * 2 + 1];
                        float p0 = acc[mt][nt ^ 2][rh * 2];
                        float p1 = acc[mt][nt ^ 2][rh * 2 + 1];
                        float r0 = (nt < 2) ? -p0 : p0;
                        float r1 = (nt < 2) ? -p1 : p1;
                        float2 v;
                        v.x = x0 * __cosf(f2.x) + r0 * __sinf(f2.x);
                        v.y = x1 * __cosf(f2.y) + r1 * __sinf(f2.y);
                        *(float2*)(orow + c) = v;
                    } else {
                        float2 v = make_float2(acc[mt][nt][rh * 2], acc[mt][nt][rh * 2 + 1]);
                        *(float2*)(orow + c) = v;
                    }
                }
            }
        }
    }
}

__global__ __launch_bounds__(256, 2) void proj_qkv_kernel(
    const float* __restrict__ q, const float* __restrict__ k,
    const float* __restrict__ v,
    const float* __restrict__ wq, const float* __restrict__ wk,
    const float* __restrict__ wv,
    const float* __restrict__ freqs,
    float* __restrict__ Qh, float* __restrict__ Kh, float* __restrict__ Vh)
{
    const int z = blockIdx.z;
    const float* X = (z == 0) ? q : (z == 1) ? k : v;
    const float* W = (z == 0) ? wq : (z == 1) ? wk : wv;
    float* out = (z == 0) ? Qh : (z == 1) ? Kh : Vh;
    proj_body(X, W, freqs, out, 1, blockIdx.x, blockIdx.y);
}

__global__ __launch_bounds__(256, 2) void proj_o_kernel(
    const float* __restrict__ X, const float* __restrict__ W,
    float* __restrict__ out)
{
    proj_body(X, W, nullptr, out, 0, blockIdx.x, blockIdx.y);
}

// ---------------------------------------------------------------------------
// Causal flash attention, tf32 + ldmatrix everywhere (V transposed in smem).
// Block = (head, 128-query tile), 256 threads = 8 warps, each warp 16 q-rows.
// smem 97KB -> 2 CTAs/SM -> 16 warps/SM.
// ---------------------------------------------------------------------------
__global__ __launch_bounds__(256, 2) void attn_kernel(
    const float* __restrict__ Q, const float* __restrict__ Kg,
    const float* __restrict__ Vg, float* __restrict__ vals)
{
    extern __shared__ uint32_t sm[];
    uint32_t* Qs = sm;                 // 128x64, xor-swizzled  (8192 w)
    uint32_t* Ks = sm + 8192;          // 64x64, xor-swizzled   (4096 w)
    uint32_t* VT = sm + 12288;         // 64 dh-rows x VS2      (4352 w)
    uint32_t* Ps = sm + 16640;         // 128x64, xor-swizzled  (8192 w)
    // total 24832 w = 99328 B

    const int tid = threadIdx.x;
    const int lane = tid & 31;
    const int w = tid >> 5;            // 0..7
    const int gid = lane >> 2;
    const int tig = lane & 3;
    const int b = 31 - blockIdx.x;     // long tiles first
    const int h = blockIdx.y;

    const int lsub = lane >> 3;
    const int lr = lane & 7;
    const int khA = lsub >> 1;
    const int khB = lsub & 1;

    const uint32_t qs_s = (uint32_t)__cvta_generic_to_shared(Qs);
    const uint32_t ks_s = (uint32_t)__cvta_generic_to_shared(Ks);
    const uint32_t vt_s = (uint32_t)__cvta_generic_to_shared(VT);
    const uint32_t ps_s = (uint32_t)__cvta_generic_to_shared(Ps);

    const int rowA = w * 16 + lr + ((lsub & 1) << 3);
    const uint32_t aQ = qs_s + rowA * 256;
    const uint32_t aP = ps_s + rowA * 256;
    const int rowBr = lr + ((lsub >> 1) << 3);
    uint32_t bK[4], bV[4];
#pragma unroll
    for (int np = 0; np < 4; np++) {
        bK[np] = ks_s + (np * 16 + rowBr) * 256;
        bV[np] = vt_s + (np * 16 + rowBr) * (VS2 * 4);
    }

    const float* Qh = Q + (size_t)h * T * DH;
    const float* Kh = Kg + (size_t)h * T * DH;
    const float* Vh = Vg + (size_t)h * T * DH;

    // Q tile (128 rows): prescale by 1/sqrt(DH)*log2(e), RNA tf32, swizzled
    const float qscale = 0.125f * 1.4426950408889634f;
#pragma unroll
    for (int i = 0; i < 8; i++) {
        int f = tid + i * 256;
        int m = f >> 4, kg = f & 15;
        float4 v4 = *(const float4*)(Qh + (size_t)(b * 128 + m) * DH + kg * 4);
        uint4 u = make_uint4(f2tf(v4.x * qscale), f2tf(v4.y * qscale),
                             f2tf(v4.z * qscale), f2tf(v4.w * qscale));
        *(uint4*)&Qs[m * 64 + ((kg ^ (m & 7)) << 2)] = u;
    }

    float o[8][4];
#pragma unroll
    for (int nt = 0; nt < 8; nt++)
#pragma unroll
        for (int r = 0; r < 4; r++) o[nt][r] = 0.f;
    float mr[2] = {-1e30f, -1e30f};
    float lr2[2] = {0.f, 0.f};

    const int n_iters = 2 * b + 2;

    for (int jb = 0; jb < n_iters; jb++) {
        __syncthreads();
        // K fill: 1024 float4 / 256 thr = 4 each, swizzled k-major
#pragma unroll
        for (int i = 0; i < 4; i++) {
            int f = tid + i * 256;
            int m = f >> 4, kg = f & 15;
            float4 k4 = *(const float4*)(Kh + (size_t)(jb * 64 + m) * DH + kg * 4);
            uint4 uk = make_uint4(f2tf(k4.x), f2tf(k4.y), f2tf(k4.z), f2tf(k4.w));
            *(uint4*)&Ks[m * 64 + ((kg ^ (m & 7)) << 2)] = uk;
        }
        // V fill TRANSPOSED: VT[dh][kv], stride VS2. lanes -> consecutive kv
        // so the 4 scalar stores per float4 hit 32 distinct banks.
#pragma unroll
        for (int i = 0; i < 4; i++) {
            int f = tid + i * 256;
            int m = f & 63;           // kv
            int kg = f >> 6;          // dh group 0..15
            float4 v4 = *(const float4*)(Vh + (size_t)(jb * 64 + m) * DH + kg * 4);
            VT[(4 * kg + 0) * VS2 + m] = f2tf(v4.x);
            VT[(4 * kg + 1) * VS2 + m] = f2tf(v4.y);
            VT[(4 * kg + 2) * VS2 + m] = f2tf(v4.z);
            VT[(4 * kg + 3) * VS2 + m] = f2tf(v4.w);
        }
        __syncthreads();

        // S = Q K^T  (16 x 64 per warp)
        float s[8][4];
#pragma unroll
        for (int nt = 0; nt < 8; nt++)
#pragma unroll
            for (int r = 0; r < 4; r++) s[nt][r] = 0.f;

#pragma unroll
        for (int ks = 0; ks < 8; ks++) {
            uint32_t a0, a1, a2, a3;
            ldsm4(a0, a1, a2, a3, aQ + (((2 * ks + khA) ^ lr) << 4));
#pragma unroll
            for (int np = 0; np < 4; np++) {
                uint32_t b00, b01, b10, b11;
                ldsm4(b00, b01, b10, b11, bK[np] + (((2 * ks + khB) ^ lr) << 4));
                mma_tf32(s[2 * np], a0, a1, a2, a3, b00, b01);
                mma_tf32(s[2 * np + 1], a0, a1, a2, a3, b10, b11);
            }
        }

        // causal mask (only last two KV tiles cross the diagonal)
        if (jb >= 2 * b) {
#pragma unroll
            for (int nt = 0; nt < 8; nt++)
#pragma unroll
                for (int r = 0; r < 4; r++) {
                    int col = jb * 64 + nt * 8 + tig * 2 + (r & 1);
                    int row = b * 128 + w * 16 + gid + ((r & 2) ? 8 : 0);
                    if (col > row) s[nt][r] = -1e30f;
                }
        }

        // online softmax (log2 domain; 2 rows/thread); l-sum deferred
#pragma unroll
        for (int half = 0; half < 2; half++) {
            float mx = -1e30f;
#pragma unroll
            for (int nt = 0; nt < 8; nt++) {
                mx = fmaxf(mx, s[nt][half * 2]);
                mx = fmaxf(mx, s[nt][half * 2 + 1]);
            }
            mx = fmaxf(mx, __shfl_xor_sync(0xffffffffu, mx, 1));
            mx = fmaxf(mx, __shfl_xor_sync(0xffffffffu, mx, 2));
            float mnew = fmaxf(mr[half], mx);
            float alpha = ex2(mr[half] - mnew);
            mr[half] = mnew;
            float rs = 0.f;
#pragma unroll
            for (int nt = 0; nt < 8; nt++) {
                float p0 = ex2(s[nt][half * 2] - mnew);
                float p1 = ex2(s[nt][half * 2 + 1] - mnew);
                s[nt][half * 2] = p0;
                s[nt][half * 2 + 1] = p1;
                rs += p0 + p1;
            }
            lr2[half] = lr2[half] * alpha + rs;
#pragma unroll
            for (int nt = 0; nt < 8; nt++) {
                o[nt][half * 2] *= alpha;
                o[nt][half * 2 + 1] *= alpha;
            }
        }

        // write P (RNA tf32) to warp-private smem rows
        {
            int ra_ = w * 16 + gid;
            int rb_ = ra_ + 8;
#pragma unroll
            for (int nt = 0; nt < 8; nt++) {
                int col = nt * 8 + tig * 2;
                uint2 p01 = make_uint2(f2tf(s[nt][0]), f2tf(s[nt][1]));
                *(uint2*)&Ps[ra_ * 64 + (col ^ ((ra_ & 7) << 2))] = p01;
                uint2 p23 = make_uint2(f2tf(s[nt][2]), f2tf(s[nt][3]));
                *(uint2*)&Ps[rb_ * 64 + (col ^ ((rb_ & 7) << 2))] = p23;
            }
        }
        __syncwarp();

        // O += P V  (both operands via ldmatrix; VT unswizzled, stride VS2)
#pragma unroll
        for (int ks = 0; ks < 8; ks++) {
            uint32_t a0, a1, a2, a3;
            ldsm4(a0, a1, a2, a3, aP + (((2 * ks + khA) ^ lr) << 4));
#pragma unroll
            for (int np = 0; np < 4; np++) {
                uint32_t b00, b01, b10, b11;
                ldsm4(b00, b01, b10, b11, bV[np] + ((2 * ks + khB) << 4));
                mma_tf32(o[2 * np], a0, a1, a2, a3, b00, b01);
                mma_tf32(o[2 * np + 1], a0, a1, a2, a3, b10, b11);
            }
        }
    }

    // epilogue: finish deferred l-sum reduction, normalize, store
    float l0 = lr2[0];
    l0 += __shfl_xor_sync(0xffffffffu, l0, 1);
    l0 += __shfl_xor_sync(0xffffffffu, l0, 2);
    float l1 = lr2[1];
    l1 += __shfl_xor_sync(0xffffffffu, l1, 1);
    l1 += __shfl_xor_sync(0xffffffffu, l1, 2);
    float inv0 = 1.f / l0;
    float inv1 = 1.f / l1;
    int t0 = b * 128 + w * 16 + gid;
    int t1 = t0 + 8;
#pragma unroll
    for (int nt = 0; nt < 8; nt++) {
        int col = h * DH + nt * 8 + tig * 2;
        float2 v0 = make_float2(o[nt][0] * inv0, o[nt][1] * inv0);
        *(float2*)(vals + (size_t)t0 * D + col) = v0;
        float2 v1 = make_float2(o[nt][2] * inv1, o[nt][3] * inv1);
        *(float2*)(vals + (size_t)t1 * D + col) = v1;
    }
}

// ---------------------------------------------------------------------------
extern "C" void kernel_launch(void* const* d_in, const int* in_sizes, int n_in,
                              void* d_out, int out_size)
{
    const float* q     = (const float*)d_in[0];
    const float* k     = (const float*)d_in[1];
    const float* v     = (const float*)d_in[2];
    // d_in[3] = mask (causal tril, known statically — unused)
    const float* freqs = (const float*)d_in[4];
    const float* w_q   = (const float*)d_in[5];
    const float* w_k   = (const float*)d_in[6];
    const float* w_v   = (const float*)d_in[7];
    const float* w_o   = (const float*)d_in[8];
    float* out = (float*)d_out;

    float *Qh, *Kh, *Vh, *Vals;
    cudaGetSymbolAddress((void**)&Qh, g_Qh);
    cudaGetSymbolAddress((void**)&Kh, g_Kh);
    cudaGetSymbolAddress((void**)&Vh, g_Vh);
    cudaGetSymbolAddress((void**)&Vals, g_Vals);

    // merged q/k/v projections + RoPE  (block tile 128x128)
    proj_qkv_kernel<<<dim3(D / 128, T / 128, 3), 256>>>(
        q, k, v, w_q, w_k, w_v, freqs, Qh, Kh, Vh);

    // attention
    size_t smem = 24832 * sizeof(uint32_t);  // 99328 B
    cudaFuncSetAttribute(attn_kernel,
                         cudaFuncAttributeMaxDynamicSharedMemorySize, (int)smem);
    attn_kernel<<<dim3(T / 128, H), 256, smem>>>(Qh, Kh, Vh, Vals);

    // output projection
    proj_o_kernel<<<dim3(D / 128, T / 128), 256>>>(Vals, w_o, out);
}

// round 10
// speedup vs baseline: 1.0632x; 1.0632x over previous
#include <cuda_runtime.h>
#include <math.h>
#include <stdint.h>

#define T 4096
#define D 1024
#define H 16
#define DH 64
#define L 32

#define VS2 68   // VT row stride in words: 68 % 32 == 4 -> conflict-free stores+ldsm

// Scratch (allocation-free rule: __device__ globals)
__device__ float g_Qh[H * T * DH];
__device__ float g_Kh[H * T * DH];
__device__ float g_Vh[H * T * DH];
__device__ float g_Vals[T * D];

__device__ __forceinline__ uint32_t f2tf(float f) {
    uint32_t r;
    asm("cvt.rna.tf32.f32 %0, %1;" : "=r"(r) : "f"(f));
    return r;
}

__device__ __forceinline__ float ex2(float f) {
    float r;
    asm("ex2.approx.f32 %0, %1;" : "=f"(r) : "f"(f));
    return r;
}

__device__ __forceinline__ void mma_tf32(float c[4], uint32_t a0, uint32_t a1,
                                         uint32_t a2, uint32_t a3,
                                         uint32_t b0, uint32_t b1) {
    asm volatile(
        "mma.sync.aligned.m16n8k8.row.col.f32.tf32.tf32.f32 "
        "{%0,%1,%2,%3}, {%4,%5,%6,%7}, {%8,%9}, {%0,%1,%2,%3};\n"
        : "+f"(c[0]), "+f"(c[1]), "+f"(c[2]), "+f"(c[3])
        : "r"(a0), "r"(a1), "r"(a2), "r"(a3), "r"(b0), "r"(b1));
}

__device__ __forceinline__ void ldsm4(uint32_t& d0, uint32_t& d1, uint32_t& d2,
                                      uint32_t& d3, uint32_t saddr) {
    asm volatile(
        "ldmatrix.sync.aligned.m8n8.x4.shared.b16 {%0,%1,%2,%3}, [%4];"
        : "=r"(d0), "=r"(d1), "=r"(d2), "=r"(d3)
        : "r"(saddr));
}

// ---------------------------------------------------------------------------
// Projection GEMM (tf32 mma.sync + ldmatrix).
// out = X[M,K] @ W[N,K]^T.  Block tile 128x128, BK=32. 256 threads = 8 warps.
// mode 0: row-major out [T,1024].
// mode 1: RoPE + head-major out [H][T][DH]; bx covers heads 2bx, 2bx+1.
// ---------------------------------------------------------------------------
__device__ __forceinline__ void proj_body(
    const float* __restrict__ X, const float* __restrict__ W,
    const float* __restrict__ freqs, float* __restrict__ out, int mode,
    int bx, int by)
{
    __shared__ uint32_t As[128 * 32];   // 16 KB
    __shared__ uint32_t Bs[128 * 32];   // 16 KB

    const int tid = threadIdx.x;
    const int lane = tid & 31;
    const int w = tid >> 5;
    const int gid = lane >> 2;
    const int tig = lane & 3;
    const int wm = w >> 1;
    const int wn = w & 1;

    const int lsub = lane >> 3;
    const int lr = lane & 7;
    const int khA = lsub >> 1;
    const int khB = lsub & 1;

    const uint32_t as_s = (uint32_t)__cvta_generic_to_shared(As);
    const uint32_t bs_s = (uint32_t)__cvta_generic_to_shared(Bs);

    uint32_t aA[2];
#pragma unroll
    for (int mt = 0; mt < 2; mt++) {
        int rowA = wm * 32 + mt * 16 + lr + ((lsub & 1) << 3);
        aA[mt] = as_s + rowA * 128;
    }
    uint32_t bB[4];
#pragma unroll
    for (int np = 0; np < 4; np++) {
        int n = wn * 64 + np * 16 + lr + ((lsub >> 1) << 3);
        bB[np] = bs_s + n * 128;
    }

    float acc[2][8][4];
#pragma unroll
    for (int mt = 0; mt < 2; mt++)
#pragma unroll
        for (int nt = 0; nt < 8; nt++)
#pragma unroll
            for (int r = 0; r < 4; r++) acc[mt][nt][r] = 0.f;

    int rows_[4], kgs_[4];
#pragma unroll
    for (int i = 0; i < 4; i++) {
        int f = tid + i * 256;
        rows_[i] = f >> 3;
        kgs_[i] = f & 7;
    }

    float4 ra[4], rb[4];
#pragma unroll
    for (int i = 0; i < 4; i++) {
        ra[i] = *(const float4*)(X + (size_t)(by * 128 + rows_[i]) * D + kgs_[i] * 4);
        rb[i] = *(const float4*)(W + (size_t)(bx * 128 + rows_[i]) * D + kgs_[i] * 4);
    }

    for (int kk = 0; kk < 32; kk++) {
        __syncthreads();
#pragma unroll
        for (int i = 0; i < 4; i++) {
            uint4 ua = make_uint4(f2tf(ra[i].x), f2tf(ra[i].y), f2tf(ra[i].z), f2tf(ra[i].w));
            *(uint4*)&As[rows_[i] * 32 + ((kgs_[i] ^ (rows_[i] & 7)) << 2)] = ua;
            uint4 ub = make_uint4(f2tf(rb[i].x), f2tf(rb[i].y), f2tf(rb[i].z), f2tf(rb[i].w));
            *(uint4*)&Bs[rows_[i] * 32 + ((kgs_[i] ^ (rows_[i] & 7)) << 2)] = ub;
        }
        __syncthreads();

        if (kk < 31) {
            int k0 = (kk + 1) * 32;
#pragma unroll
            for (int i = 0; i < 4; i++) {
                ra[i] = *(const float4*)(X + (size_t)(by * 128 + rows_[i]) * D + k0 + kgs_[i] * 4);
                rb[i] = *(const float4*)(W + (size_t)(bx * 128 + rows_[i]) * D + k0 + kgs_[i] * 4);
            }
        }

#pragma unroll
        for (int ks = 0; ks < 4; ks++) {
            uint32_t a[2][4];
#pragma unroll
            for (int mt = 0; mt < 2; mt++)
                ldsm4(a[mt][0], a[mt][1], a[mt][2], a[mt][3],
                      aA[mt] + (((2 * ks + khA) ^ lr) << 4));
#pragma unroll
            for (int np = 0; np < 4; np++) {
                uint32_t b00, b01, b10, b11;
                ldsm4(b00, b01, b10, b11, bB[np] + (((2 * ks + khB) ^ lr) << 4));
#pragma unroll
                for (int mt = 0; mt < 2; mt++) {
                    mma_tf32(acc[mt][2 * np], a[mt][0], a[mt][1], a[mt][2], a[mt][3], b00, b01);
                    mma_tf32(acc[mt][2 * np + 1], a[mt][0], a[mt][1], a[mt][2], a[mt][3], b10, b11);
                }
            }
        }
    }

    if (mode == 0) {
#pragma unroll
        for (int mt = 0; mt < 2; mt++) {
#pragma unroll
            for (int rh = 0; rh < 2; rh++) {
                int t = by * 128 + wm * 32 + mt * 16 + gid + rh * 8;
#pragma unroll
                for (int nt = 0; nt < 8; nt++) {
                    int col = bx * 128 + wn * 64 + nt * 8 + tig * 2;
                    float2 v = make_float2(acc[mt][nt][rh * 2], acc[mt][nt][rh * 2 + 1]);
                    *(float2*)(out + (size_t)t * D + col) = v;
                }
            }
        }
    } else {
        const int h = bx * 2 + wn;
#pragma unroll
        for (int mt = 0; mt < 2; mt++) {
#pragma unroll
            for (int rh = 0; rh < 2; rh++) {
                int t = by * 128 + wm * 32 + mt * 16 + gid + rh * 8;
                float* orow = out + (size_t)h * T * DH + (size_t)t * DH;
#pragma unroll
                for (int nt = 0; nt < 8; nt++) {
                    int c = nt * 8 + tig * 2;
                    if (nt < 4) {
                        float2 f2 = *(const float2*)(freqs + (size_t)t * L + c);
                        float x0 = acc[mt][nt][rh * 2];
                        float x1 = acc[mt][nt][rh * 2 + 1];
                        float p0 = acc[mt][nt ^ 2][rh * 2];
                        float p1 = acc[mt][nt ^ 2][rh * 2 + 1];
                        float r0 = (nt < 2) ? -p0 : p0;
                        float r1 = (nt < 2) ? -p1 : p1;
                        float2 v;
                        v.x = x0 * __cosf(f2.x) + r0 * __sinf(f2.x);
                        v.y = x1 * __cosf(f2.y) + r1 * __sinf(f2.y);
                        *(float2*)(orow + c) = v;
                    } else {
                        float2 v = make_float2(acc[mt][nt][rh * 2], acc[mt][nt][rh * 2 + 1]);
                        *(float2*)(orow + c) = v;
                    }
                }
            }
        }
    }
}

__global__ __launch_bounds__(256, 2) void proj_qkv_kernel(
    const float* __restrict__ q, const float* __restrict__ k,
    const float* __restrict__ v,
    const float* __restrict__ wq, const float* __restrict__ wk,
    const float* __restrict__ wv,
    const float* __restrict__ freqs,
    float* __restrict__ Qh, float* __restrict__ Kh, float* __restrict__ Vh)
{
    const int z = blockIdx.z;
    const float* X = (z == 0) ? q : (z == 1) ? k : v;
    const float* W = (z == 0) ? wq : (z == 1) ? wk : wv;
    float* out = (z == 0) ? Qh : (z == 1) ? Kh : Vh;
    proj_body(X, W, freqs, out, 1, blockIdx.x, blockIdx.y);
}

__global__ __launch_bounds__(256, 2) void proj_o_kernel(
    const float* __restrict__ X, const float* __restrict__ W,
    float* __restrict__ out)
{
    proj_body(X, W, nullptr, out, 0, blockIdx.x, blockIdx.y);
}

// ---------------------------------------------------------------------------
// Causal flash attention, tf32 + ldmatrix (V transposed -> ldmatrix too).
// Block = (head, 128-query tile), 128 threads = 4 warps, each warp 32 q-rows
// (mt=2) -> every K/V B-fragment feeds 2 MMAs.
// ---------------------------------------------------------------------------
__global__ __launch_bounds__(128) void attn_kernel(
    const float* __restrict__ Q, const float* __restrict__ Kg,
    const float* __restrict__ Vg, float* __restrict__ vals)
{
    extern __shared__ uint32_t sm[];
    uint32_t* Qs = sm;                 // 128x64, xor-swizzled  (8192 w)
    uint32_t* Ks = sm + 8192;          // 64x64, xor-swizzled   (4096 w)
    uint32_t* VT = sm + 12288;         // 64 dh-rows x VS2      (4352 w)
    uint32_t* Ps = sm + 16640;         // 128x64, xor-swizzled  (8192 w)
    // total 24832 w = 99328 B

    const int tid = threadIdx.x;
    const int lane = tid & 31;
    const int w = tid >> 5;
    const int gid = lane >> 2;
    const int tig = lane & 3;
    const int b = 31 - blockIdx.x;     // long tiles first
    const int h = blockIdx.y;

    const int lsub = lane >> 3;
    const int lr = lane & 7;
    const int khA = lsub >> 1;
    const int khB = lsub & 1;

    const uint32_t qs_s = (uint32_t)__cvta_generic_to_shared(Qs);
    const uint32_t ks_s = (uint32_t)__cvta_generic_to_shared(Ks);
    const uint32_t vt_s = (uint32_t)__cvta_generic_to_shared(VT);
    const uint32_t ps_s = (uint32_t)__cvta_generic_to_shared(Ps);

    uint32_t aQ[2], aP[2];
#pragma unroll
    for (int mt = 0; mt < 2; mt++) {
        int rowA = w * 32 + mt * 16 + lr + ((lsub & 1) << 3);
        aQ[mt] = qs_s + rowA * 256;
        aP[mt] = ps_s + rowA * 256;
    }
    const int rowBr = lr + ((lsub >> 1) << 3);
    uint32_t bK[4], bV[4];
#pragma unroll
    for (int np = 0; np < 4; np++) {
        bK[np] = ks_s + (np * 16 + rowBr) * 256;
        bV[np] = vt_s + (np * 16 + rowBr) * (VS2 * 4);
    }

    const float* Qh = Q + (size_t)h * T * DH;
    const float* Kh = Kg + (size_t)h * T * DH;
    const float* Vh = Vg + (size_t)h * T * DH;

    const float qscale = 0.125f * 1.4426950408889634f;  // 1/sqrt(DH) * log2(e)
#pragma unroll
    for (int i = 0; i < 16; i++) {
        int f = tid + i * 128;
        int m = f >> 4, kg = f & 15;
        float4 v4 = *(const float4*)(Qh + (size_t)(b * 128 + m) * DH + kg * 4);
        uint4 u = make_uint4(f2tf(v4.x * qscale), f2tf(v4.y * qscale),
                             f2tf(v4.z * qscale), f2tf(v4.w * qscale));
        *(uint4*)&Qs[m * 64 + ((kg ^ (m & 7)) << 2)] = u;
    }

    float o[2][8][4];
#pragma unroll
    for (int mt = 0; mt < 2; mt++)
#pragma unroll
        for (int nt = 0; nt < 8; nt++)
#pragma unroll
            for (int r = 0; r < 4; r++) o[mt][nt][r] = 0.f;
    float mr[2][2] = {{-1e30f, -1e30f}, {-1e30f, -1e30f}};
    float lr2[2][2] = {{0.f, 0.f}, {0.f, 0.f}};

    const int n_iters = 2 * b + 2;

    for (int jb = 0; jb < n_iters; jb++) {
        __syncthreads();
        // K fill: 1024 float4 / 128 thr = 8 each, swizzled k-major
#pragma unroll
        for (int i = 0; i < 8; i++) {
            int f = tid + i * 128;
            int m = f >> 4, kg = f & 15;
            float4 k4 = *(const float4*)(Kh + (size_t)(jb * 64 + m) * DH + kg * 4);
            uint4 uk = make_uint4(f2tf(k4.x), f2tf(k4.y), f2tf(k4.z), f2tf(k4.w));
            *(uint4*)&Ks[m * 64 + ((kg ^ (m & 7)) << 2)] = uk;
        }
        // V fill TRANSPOSED: VT[dh][kv], stride VS2; lanes -> consecutive kv
        // so the 4 scalar stores per float4 hit 32 distinct banks.
#pragma unroll
        for (int i = 0; i < 8; i++) {
            int f = tid + i * 128;
            int m = f & 63;           // kv
            int kg = f >> 6;          // dh group 0..15
            float4 v4 = *(const float4*)(Vh + (size_t)(jb * 64 + m) * DH + kg * 4);
            VT[(4 * kg + 0) * VS2 + m] = f2tf(v4.x);
            VT[(4 * kg + 1) * VS2 + m] = f2tf(v4.y);
            VT[(4 * kg + 2) * VS2 + m] = f2tf(v4.z);
            VT[(4 * kg + 3) * VS2 + m] = f2tf(v4.w);
        }
        __syncthreads();

        // S = Q K^T  (32 x 64 per warp, B fragments reused across mt)
        float s[2][8][4];
#pragma unroll
        for (int mt = 0; mt < 2; mt++)
#pragma unroll
            for (int nt = 0; nt < 8; nt++)
#pragma unroll
                for (int r = 0; r < 4; r++) s[mt][nt][r] = 0.f;

#pragma unroll
        for (int ks = 0; ks < 8; ks++) {
            uint32_t a[2][4];
#pragma unroll
            for (int mt = 0; mt < 2; mt++)
                ldsm4(a[mt][0], a[mt][1], a[mt][2], a[mt][3],
                      aQ[mt] + (((2 * ks + khA) ^ lr) << 4));
#pragma unroll
            for (int np = 0; np < 4; np++) {
                uint32_t b00, b01, b10, b11;
                ldsm4(b00, b01, b10, b11, bK[np] + (((2 * ks + khB) ^ lr) << 4));
#pragma unroll
                for (int mt = 0; mt < 2; mt++) {
                    mma_tf32(s[mt][2 * np], a[mt][0], a[mt][1], a[mt][2], a[mt][3], b00, b01);
                    mma_tf32(s[mt][2 * np + 1], a[mt][0], a[mt][1], a[mt][2], a[mt][3], b10, b11);
                }
            }
        }

        if (jb >= 2 * b) {
#pragma unroll
            for (int mt = 0; mt < 2; mt++)
#pragma unroll
                for (int nt = 0; nt < 8; nt++)
#pragma unroll
                    for (int r = 0; r < 4; r++) {
                        int col = jb * 64 + nt * 8 + tig * 2 + (r & 1);
                        int row = b * 128 + w * 32 + mt * 16 + gid + ((r & 2) ? 8 : 0);
                        if (col > row) s[mt][nt][r] = -1e30f;
                    }
        }

#pragma unroll
        for (int mt = 0; mt < 2; mt++) {
#pragma unroll
            for (int half = 0; half < 2; half++) {
                float mx = -1e30f;
#pragma unroll
                for (int nt = 0; nt < 8; nt++) {
                    mx = fmaxf(mx, s[mt][nt][half * 2]);
                    mx = fmaxf(mx, s[mt][nt][half * 2 + 1]);
                }
                mx = fmaxf(mx, __shfl_xor_sync(0xffffffffu, mx, 1));
                mx = fmaxf(mx, __shfl_xor_sync(0xffffffffu, mx, 2));
                float mnew = fmaxf(mr[mt][half], mx);
                float alpha = ex2(mr[mt][half] - mnew);
                mr[mt][half] = mnew;
                float rs = 0.f;
#pragma unroll
                for (int nt = 0; nt < 8; nt++) {
                    float p0 = ex2(s[mt][nt][half * 2] - mnew);
                    float p1 = ex2(s[mt][nt][half * 2 + 1] - mnew);
                    s[mt][nt][half * 2] = p0;
                    s[mt][nt][half * 2 + 1] = p1;
                    rs += p0 + p1;
                }
                lr2[mt][half] = lr2[mt][half] * alpha + rs;
#pragma unroll
                for (int nt = 0; nt < 8; nt++) {
                    o[mt][nt][half * 2] *= alpha;
                    o[mt][nt][half * 2 + 1] *= alpha;
                }
            }

            int ra_ = w * 32 + mt * 16 + gid;
            int rb_ = ra_ + 8;
#pragma unroll
            for (int nt = 0; nt < 8; nt++) {
                int col = nt * 8 + tig * 2;
                uint2 p01 = make_uint2(f2tf(s[mt][nt][0]), f2tf(s[mt][nt][1]));
                *(uint2*)&Ps[ra_ * 64 + (col ^ ((ra_ & 7) << 2))] = p01;
                uint2 p23 = make_uint2(f2tf(s[mt][nt][2]), f2tf(s[mt][nt][3]));
                *(uint2*)&Ps[rb_ * 64 + (col ^ ((rb_ & 7) << 2))] = p23;
            }
        }
        __syncwarp();

        // O += P V  (P and V both via ldmatrix; V fragments reused across mt)
#pragma unroll
        for (int ks = 0; ks < 8; ks++) {
            uint32_t a[2][4];
#pragma unroll
            for (int mt = 0; mt < 2; mt++)
                ldsm4(a[mt][0], a[mt][1], a[mt][2], a[mt][3],
                      aP[mt] + (((2 * ks + khA) ^ lr) << 4));
#pragma unroll
            for (int np = 0; np < 4; np++) {
                uint32_t b00, b01, b10, b11;
                ldsm4(b00, b01, b10, b11, bV[np] + ((2 * ks + khB) << 4));
#pragma unroll
                for (int mt = 0; mt < 2; mt++) {
                    mma_tf32(o[mt][2 * np], a[mt][0], a[mt][1], a[mt][2], a[mt][3], b00, b01);
                    mma_tf32(o[mt][2 * np + 1], a[mt][0], a[mt][1], a[mt][2], a[mt][3], b10, b11);
                }
            }
        }
    }

    // epilogue: finish deferred l-sum reduction, normalize, store
#pragma unroll
    for (int mt = 0; mt < 2; mt++) {
        float l0 = lr2[mt][0];
        l0 += __shfl_xor_sync(0xffffffffu, l0, 1);
        l0 += __shfl_xor_sync(0xffffffffu, l0, 2);
        float l1 = lr2[mt][1];
        l1 += __shfl_xor_sync(0xffffffffu, l1, 1);
        l1 += __shfl_xor_sync(0xffffffffu, l1, 2);
        float inv0 = 1.f / l0;
        float inv1 = 1.f / l1;
        int t0 = b * 128 + w * 32 + mt * 16 + gid;
        int t1 = t0 + 8;
#pragma unroll
        for (int nt = 0; nt < 8; nt++) {
            int col = h * DH + nt * 8 + tig * 2;
            float2 v0 = make_float2(o[mt][nt][0] * inv0, o[mt][nt][1] * inv0);
            *(float2*)(vals + (size_t)t0 * D + col) = v0;
            float2 v1 = make_float2(o[mt][nt][2] * inv1, o[mt][nt][3] * inv1);
            *(float2*)(vals + (size_t)t1 * D + col) = v1;
        }
    }
}

// ---------------------------------------------------------------------------
extern "C" void kernel_launch(void* const* d_in, const int* in_sizes, int n_in,
                              void* d_out, int out_size)
{
    const float* q     = (const float*)d_in[0];
    const float* k     = (const float*)d_in[1];
    const float* v     = (const float*)d_in[2];
    // d_in[3] = mask (causal tril, known statically — unused)
    const float* freqs = (const float*)d_in[4];
    const float* w_q   = (const float*)d_in[5];
    const float* w_k   = (const float*)d_in[6];
    const float* w_v   = (const float*)d_in[7];
    const float* w_o   = (const float*)d_in[8];
    float* out = (float*)d_out;

    float *Qh, *Kh, *Vh, *Vals;
    cudaGetSymbolAddress((void**)&Qh, g_Qh);
    cudaGetSymbolAddress((void**)&Kh, g_Kh);
    cudaGetSymbolAddress((void**)&Vh, g_Vh);
    cudaGetSymbolAddress((void**)&Vals, g_Vals);

    // merged q/k/v projections + RoPE  (block tile 128x128)
    proj_qkv_kernel<<<dim3(D / 128, T / 128, 3), 256>>>(
        q, k, v, w_q, w_k, w_v, freqs, Qh, Kh, Vh);

    // attention
    size_t smem = 24832 * sizeof(uint32_t);  // 99328 B
    cudaFuncSetAttribute(attn_kernel,
                         cudaFuncAttributeMaxDynamicSharedMemorySize, (int)smem);
    attn_kernel<<<dim3(T / 128, H), 128, smem>>>(Qh, Kh, Vh, Vals);

    // output projection
    proj_o_kernel<<<dim3(D / 128, T / 128), 256>>>(Vals, w_o, out);
}

// round 12
// speedup vs baseline: 1.1948x; 1.1238x over previous
#include <cuda_runtime.h>
#include <math.h>
#include <stdint.h>

#define T 4096
#define D 1024
#define H 16
#define DH 64
#define L 32

#define VSTR 72   // V smem row stride in words: 72 % 32 == 8 -> conflict-free scalar reads

// Scratch (allocation-free rule: __device__ globals)
__device__ float g_Qh[H * T * DH];
__device__ float g_Kh[H * T * DH];
__device__ float g_Vh[H * T * DH];
__device__ float g_Vals[T * D];

__device__ __forceinline__ uint32_t f2tf(float f) {
    uint32_t r;
    asm("cvt.rna.tf32.f32 %0, %1;" : "=r"(r) : "f"(f));
    return r;
}

__device__ __forceinline__ float ex2(float f) {
    float r;
    asm("ex2.approx.f32 %0, %1;" : "=f"(r) : "f"(f));
    return r;
}

__device__ __forceinline__ void mma_tf32(float c[4], uint32_t a0, uint32_t a1,
                                         uint32_t a2, uint32_t a3,
                                         uint32_t b0, uint32_t b1) {
    asm volatile(
        "mma.sync.aligned.m16n8k8.row.col.f32.tf32.tf32.f32 "
        "{%0,%1,%2,%3}, {%4,%5,%6,%7}, {%8,%9}, {%0,%1,%2,%3};\n"
        : "+f"(c[0]), "+f"(c[1]), "+f"(c[2]), "+f"(c[3])
        : "r"(a0), "r"(a1), "r"(a2), "r"(a3), "r"(b0), "r"(b1));
}

__device__ __forceinline__ void ldsm4(uint32_t& d0, uint32_t& d1, uint32_t& d2,
                                      uint32_t& d3, uint32_t saddr) {
    asm volatile(
        "ldmatrix.sync.aligned.m8n8.x4.shared.b16 {%0,%1,%2,%3}, [%4];"
        : "=r"(d0), "=r"(d1), "=r"(d2), "=r"(d3)
        : "r"(saddr));
}

// ---------------------------------------------------------------------------
// Projection GEMM (tf32 mma.sync + ldmatrix).
// out = X[M,K] @ W[N,K]^T.  Block tile 128x128, BK=32. 256 threads = 8 warps.
// mode 0: row-major out [T,1024].
// mode 1: RoPE + head-major out [H][T][DH]; bx covers heads 2bx, 2bx+1.
// ---------------------------------------------------------------------------
__device__ __forceinline__ void proj_body(
    const float* __restrict__ X, const float* __restrict__ W,
    const float* __restrict__ freqs, float* __restrict__ out, int mode,
    int bx, int by)
{
    __shared__ uint32_t As[128 * 32];   // 16 KB
    __shared__ uint32_t Bs[128 * 32];   // 16 KB

    const int tid = threadIdx.x;
    const int lane = tid & 31;
    const int w = tid >> 5;
    const int gid = lane >> 2;
    const int tig = lane & 3;
    const int wm = w >> 1;
    const int wn = w & 1;

    const int lsub = lane >> 3;
    const int lr = lane & 7;
    const int khA = lsub >> 1;
    const int khB = lsub & 1;

    const uint32_t as_s = (uint32_t)__cvta_generic_to_shared(As);
    const uint32_t bs_s = (uint32_t)__cvta_generic_to_shared(Bs);

    uint32_t aA[2];
#pragma unroll
    for (int mt = 0; mt < 2; mt++) {
        int rowA = wm * 32 + mt * 16 + lr + ((lsub & 1) << 3);
        aA[mt] = as_s + rowA * 128;
    }
    uint32_t bB[4];
#pragma unroll
    for (int np = 0; np < 4; np++) {
        int n = wn * 64 + np * 16 + lr + ((lsub >> 1) << 3);
        bB[np] = bs_s + n * 128;
    }

    float acc[2][8][4];
#pragma unroll
    for (int mt = 0; mt < 2; mt++)
#pragma unroll
        for (int nt = 0; nt < 8; nt++)
#pragma unroll
            for (int r = 0; r < 4; r++) acc[mt][nt][r] = 0.f;

    int rows_[4], kgs_[4];
#pragma unroll
    for (int i = 0; i < 4; i++) {
        int f = tid + i * 256;
        rows_[i] = f >> 3;
        kgs_[i] = f & 7;
    }

    float4 ra[4], rb[4];
#pragma unroll
    for (int i = 0; i < 4; i++) {
        ra[i] = *(const float4*)(X + (size_t)(by * 128 + rows_[i]) * D + kgs_[i] * 4);
        rb[i] = *(const float4*)(W + (size_t)(bx * 128 + rows_[i]) * D + kgs_[i] * 4);
    }

    for (int kk = 0; kk < 32; kk++) {
        __syncthreads();
#pragma unroll
        for (int i = 0; i < 4; i++) {
            uint4 ua = make_uint4(f2tf(ra[i].x), f2tf(ra[i].y), f2tf(ra[i].z), f2tf(ra[i].w));
            *(uint4*)&As[rows_[i] * 32 + ((kgs_[i] ^ (rows_[i] & 7)) << 2)] = ua;
            uint4 ub = make_uint4(f2tf(rb[i].x), f2tf(rb[i].y), f2tf(rb[i].z), f2tf(rb[i].w));
            *(uint4*)&Bs[rows_[i] * 32 + ((kgs_[i] ^ (rows_[i] & 7)) << 2)] = ub;
        }
        __syncthreads();

        if (kk < 31) {
            int k0 = (kk + 1) * 32;
#pragma unroll
            for (int i = 0; i < 4; i++) {
                ra[i] = *(const float4*)(X + (size_t)(by * 128 + rows_[i]) * D + k0 + kgs_[i] * 4);
                rb[i] = *(const float4*)(W + (size_t)(bx * 128 + rows_[i]) * D + k0 + kgs_[i] * 4);
            }
        }

#pragma unroll
        for (int ks = 0; ks < 4; ks++) {
            uint32_t a[2][4];
#pragma unroll
            for (int mt = 0; mt < 2; mt++)
                ldsm4(a[mt][0], a[mt][1], a[mt][2], a[mt][3],
                      aA[mt] + (((2 * ks + khA) ^ lr) << 4));
#pragma unroll
            for (int np = 0; np < 4; np++) {
                uint32_t b00, b01, b10, b11;
                ldsm4(b00, b01, b10, b11, bB[np] + (((2 * ks + khB) ^ lr) << 4));
#pragma unroll
                for (int mt = 0; mt < 2; mt++) {
                    mma_tf32(acc[mt][2 * np], a[mt][0], a[mt][1], a[mt][2], a[mt][3], b00, b01);
                    mma_tf32(acc[mt][2 * np + 1], a[mt][0], a[mt][1], a[mt][2], a[mt][3], b10, b11);
                }
            }
        }
    }

    if (mode == 0) {
#pragma unroll
        for (int mt = 0; mt < 2; mt++) {
#pragma unroll
            for (int rh = 0; rh < 2; rh++) {
                int t = by * 128 + wm * 32 + mt * 16 + gid + rh * 8;
#pragma unroll
                for (int nt = 0; nt < 8; nt++) {
                    int col = bx * 128 + wn * 64 + nt * 8 + tig * 2;
                    float2 v = make_float2(acc[mt][nt][rh * 2], acc[mt][nt][rh * 2 + 1]);
                    *(float2*)(out + (size_t)t * D + col) = v;
                }
            }
        }
    } else {
        const int h = bx * 2 + wn;
#pragma unroll
        for (int mt = 0; mt < 2; mt++) {
#pragma unroll
            for (int rh = 0; rh < 2; rh++) {
                int t = by * 128 + wm * 32 + mt * 16 + gid + rh * 8;
                float* orow = out + (size_t)h * T * DH + (size_t)t * DH;
#pragma unroll
                for (int nt = 0; nt < 8; nt++) {
                    int c = nt * 8 + tig * 2;
                    if (nt < 4) {
                        float2 f2 = *(const float2*)(freqs + (size_t)t * L + c);
                        float x0 = acc[mt][nt][rh * 2];
                        float x1 = acc[mt][nt][rh * 2 + 1];
                        float p0 = acc[mt][nt ^ 2][rh * 2];
                        float p1 = acc[mt][nt ^ 2][rh * 2 + 1];
                        float r0 = (nt < 2) ? -p0 : p0;
                        float r1 = (nt < 2) ? -p1 : p1;
                        float2 v;
                        v.x = x0 * __cosf(f2.x) + r0 * __sinf(f2.x);
                        v.y = x1 * __cosf(f2.y) + r1 * __sinf(f2.y);
                        *(float2*)(orow + c) = v;
                    } else {
                        float2 v = make_float2(acc[mt][nt][rh * 2], acc[mt][nt][rh * 2 + 1]);
                        *(float2*)(orow + c) = v;
                    }
                }
            }
        }
    }
}

__global__ __launch_bounds__(256, 2) void proj_qkv_kernel(
    const float* __restrict__ q, const float* __restrict__ k,
    const float* __restrict__ v,
    const float* __restrict__ wq, const float* __restrict__ wk,
    const float* __restrict__ wv,
    const float* __restrict__ freqs,
    float* __restrict__ Qh, float* __restrict__ Kh, float* __restrict__ Vh)
{
    const int z = blockIdx.z;
    const float* X = (z == 0) ? q : (z == 1) ? k : v;
    const float* W = (z == 0) ? wq : (z == 1) ? wk : wv;
    float* out = (z == 0) ? Qh : (z == 1) ? Kh : Vh;
    proj_body(X, W, freqs, out, 1, blockIdx.x, blockIdx.y);
}

__global__ __launch_bounds__(256, 2) void proj_o_kernel(
    const float* __restrict__ X, const float* __restrict__ W,
    float* __restrict__ out)
{
    proj_body(X, W, nullptr, out, 0, blockIdx.x, blockIdx.y);
}

// ---------------------------------------------------------------------------
// Causal flash attention, tf32 tensor cores + ldmatrix (R8 layout).
// Block = (head, 128-query tile), 128 threads = 4 warps, each warp 32 q-rows
// (mt=2). K/V LDG issued BEFORE the barrier (latency overlapped with the
// previous iteration's tail); staging registers reuse the dead s[] range.
// ---------------------------------------------------------------------------
__global__ __launch_bounds__(128) void attn_kernel(
    const float* __restrict__ Q, const float* __restrict__ Kg,
    const float* __restrict__ Vg, float* __restrict__ vals)
{
    extern __shared__ uint32_t sm[];
    uint32_t* Qs = sm;                 // 128x64, xor-swizzled  (8192 w)
    uint32_t* Ks = sm + 8192;          // 64x64, xor-swizzled   (4096 w)
    uint32_t* Vs = sm + 12288;         // 64 rows x VSTR        (4608 w)
    uint32_t* Ps = sm + 16896;         // 128x64, xor-swizzled  (8192 w)
    // total 25088 w = 100352 B

    const int tid = threadIdx.x;
    const int lane = tid & 31;
    const int w = tid >> 5;
    const int gid = lane >> 2;
    const int tig = lane & 3;
    const int b = 31 - blockIdx.x;     // long tiles first
    const int h = blockIdx.y;

    const int lsub = lane >> 3;
    const int lr = lane & 7;
    const int khA = lsub >> 1;
    const int khB = lsub & 1;

    const uint32_t qs_s = (uint32_t)__cvta_generic_to_shared(Qs);
    const uint32_t ks_s = (uint32_t)__cvta_generic_to_shared(Ks);
    const uint32_t ps_s = (uint32_t)__cvta_generic_to_shared(Ps);

    uint32_t aQ[2], aP[2];
#pragma unroll
    for (int mt = 0; mt < 2; mt++) {
        int rowA = w * 32 + mt * 16 + lr + ((lsub & 1) << 3);
        aQ[mt] = qs_s + rowA * 256;
        aP[mt] = ps_s + rowA * 256;
    }
    const int rowBr = lr + ((lsub >> 1) << 3);
    uint32_t bK[4];
#pragma unroll
    for (int np = 0; np < 4; np++)
        bK[np] = ks_s + (np * 16 + rowBr) * 256;

    const float* Qh = Q + (size_t)h * T * DH;
    const float* Kh = Kg + (size_t)h * T * DH;
    const float* Vh = Vg + (size_t)h * T * DH;

    // fill constants: per-thread base row/kgroup; swizzle term invariant in i
    const int m0 = tid >> 4;          // 0..7
    const int kg0 = tid & 15;
    const float* Kp = Kh + (size_t)m0 * DH + kg0 * 4;
    const float* Vp = Vh + (size_t)m0 * DH + kg0 * 4;
    uint32_t* ksw = &Ks[m0 * 64 + ((kg0 ^ (m0 & 7)) << 2)];   // +i*512
    uint32_t* vsw = &Vs[m0 * VSTR + kg0 * 4];                 // +i*8*VSTR

    // Q tile: prescale by 1/sqrt(DH)*log2(e), RNA tf32, swizzled
    const float qscale = 0.125f * 1.4426950408889634f;
#pragma unroll
    for (int i = 0; i < 16; i++) {
        int f = tid + i * 128;
        int m = f >> 4, kg = f & 15;
        float4 v4 = *(const float4*)(Qh + (size_t)(b * 128 + m) * DH + kg * 4);
        uint4 u = make_uint4(f2tf(v4.x * qscale), f2tf(v4.y * qscale),
                             f2tf(v4.z * qscale), f2tf(v4.w * qscale));
        *(uint4*)&Qs[m * 64 + ((kg ^ (m & 7)) << 2)] = u;
    }

    float o[2][8][4];
#pragma unroll
    for (int mt = 0; mt < 2; mt++)
#pragma unroll
        for (int nt = 0; nt < 8; nt++)
#pragma unroll
            for (int r = 0; r < 4; r++) o[mt][nt][r] = 0.f;
    float mr[2][2] = {{-1e30f, -1e30f}, {-1e30f, -1e30f}};
    float lr2[2][2] = {{0.f, 0.f}, {0.f, 0.f}};

    const int n_iters = 2 * b + 2;

    for (int jb = 0; jb < n_iters; jb++) {
        // prefetch K/V for this tile into registers BEFORE the barrier
        // (s[] range is dead here; LDG latency overlaps other warps' PV tail)
        float4 kr[8], vr[8];
#pragma unroll
        for (int i = 0; i < 8; i++) {
            kr[i] = *(const float4*)(Kp + (size_t)i * 8 * DH);
            vr[i] = *(const float4*)(Vp + (size_t)i * 8 * DH);
        }
        Kp += (size_t)64 * DH;
        Vp += (size_t)64 * DH;

        __syncthreads();   // prior iter's K/V reads complete
#pragma unroll
        for (int i = 0; i < 8; i++) {
            uint4 uk = make_uint4(f2tf(kr[i].x), f2tf(kr[i].y), f2tf(kr[i].z), f2tf(kr[i].w));
            *(uint4*)(ksw + i * 512) = uk;
            uint4 uv = make_uint4(f2tf(vr[i].x), f2tf(vr[i].y), f2tf(vr[i].z), f2tf(vr[i].w));
            *(uint4*)(vsw + i * 8 * VSTR) = uv;
        }
        __syncthreads();

        // S = Q K^T  (32 x 64 per warp, B fragments reused across mt)
        float s[2][8][4];
#pragma unroll
        for (int mt = 0; mt < 2; mt++)
#pragma unroll
            for (int nt = 0; nt < 8; nt++)
#pragma unroll
                for (int r = 0; r < 4; r++) s[mt][nt][r] = 0.f;

#pragma unroll
        for (int ks = 0; ks < 8; ks++) {
            uint32_t a[2][4];
#pragma unroll
            for (int mt = 0; mt < 2; mt++)
                ldsm4(a[mt][0], a[mt][1], a[mt][2], a[mt][3],
                      aQ[mt] + (((2 * ks + khA) ^ lr) << 4));
#pragma unroll
            for (int np = 0; np < 4; np++) {
                uint32_t b00, b01, b10, b11;
                ldsm4(b00, b01, b10, b11, bK[np] + (((2 * ks + khB) ^ lr) << 4));
#pragma unroll
                for (int mt = 0; mt < 2; mt++) {
                    mma_tf32(s[mt][2 * np], a[mt][0], a[mt][1], a[mt][2], a[mt][3], b00, b01);
                    mma_tf32(s[mt][2 * np + 1], a[mt][0], a[mt][1], a[mt][2], a[mt][3], b10, b11);
                }
            }
        }

        // causal mask (only last two KV tiles cross the diagonal)
        if (jb >= 2 * b) {
#pragma unroll
            for (int mt = 0; mt < 2; mt++)
#pragma unroll
                for (int nt = 0; nt < 8; nt++)
#pragma unroll
                    for (int r = 0; r < 4; r++) {
                        int col = jb * 64 + nt * 8 + tig * 2 + (r & 1);
                        int row = b * 128 + w * 32 + mt * 16 + gid + ((r & 2) ? 8 : 0);
                        if (col > row) s[mt][nt][r] = -1e30f;
                    }
        }

        // online softmax (log2 domain; two rows per thread per mt)
#pragma unroll
        for (int mt = 0; mt < 2; mt++) {
#pragma unroll
            for (int half = 0; half < 2; half++) {
                float mx = -1e30f;
#pragma unroll
                for (int nt = 0; nt < 8; nt++) {
                    mx = fmaxf(mx, s[mt][nt][half * 2]);
                    mx = fmaxf(mx, s[mt][nt][half * 2 + 1]);
                }
                mx = fmaxf(mx, __shfl_xor_sync(0xffffffffu, mx, 1));
                mx = fmaxf(mx, __shfl_xor_sync(0xffffffffu, mx, 2));
                float mnew = fmaxf(mr[mt][half], mx);
                float alpha = ex2(mr[mt][half] - mnew);
                mr[mt][half] = mnew;
                float rs = 0.f;
#pragma unroll
                for (int nt = 0; nt < 8; nt++) {
                    float p0 = ex2(s[mt][nt][half * 2] - mnew);
                    float p1 = ex2(s[mt][nt][half * 2 + 1] - mnew);
                    s[mt][nt][half * 2] = p0;
                    s[mt][nt][half * 2 + 1] = p1;
                    rs += p0 + p1;
                }
                lr2[mt][half] = lr2[mt][half] * alpha + rs;
#pragma unroll
                for (int nt = 0; nt < 8; nt++) {
                    o[mt][nt][half * 2] *= alpha;
                    o[mt][nt][half * 2 + 1] *= alpha;
                }
            }

            // write P (RNA tf32) to warp-private smem rows
            int ra_ = w * 32 + mt * 16 + gid;
            int rb_ = ra_ + 8;
#pragma unroll
            for (int nt = 0; nt < 8; nt++) {
                int col = nt * 8 + tig * 2;
                uint2 p01 = make_uint2(f2tf(s[mt][nt][0]), f2tf(s[mt][nt][1]));
                *(uint2*)&Ps[ra_ * 64 + (col ^ ((ra_ & 7) << 2))] = p01;
                uint2 p23 = make_uint2(f2tf(s[mt][nt][2]), f2tf(s[mt][nt][3]));
                *(uint2*)&Ps[rb_ * 64 + (col ^ ((rb_ & 7) << 2))] = p23;
            }
        }
        __syncwarp();

        // O += P V  (P via ldmatrix; V scalar, stride-72 conflict-free;
        //            V fragments reused across mt)
#pragma unroll
        for (int ks = 0; ks < 8; ks++) {
            int kb = ks * 8;
            uint32_t a[2][4];
#pragma unroll
            for (int mt = 0; mt < 2; mt++)
                ldsm4(a[mt][0], a[mt][1], a[mt][2], a[mt][3],
                      aP[mt] + (((2 * ks + khA) ^ lr) << 4));
            int kr0 = kb + tig, kr1 = kb + tig + 4;
            const uint32_t* vrow0 = Vs + kr0 * VSTR + gid;
            const uint32_t* vrow1 = Vs + kr1 * VSTR + gid;
#pragma unroll
            for (int nt = 0; nt < 8; nt++) {
                uint32_t b0 = vrow0[nt * 8];
                uint32_t b1 = vrow1[nt * 8];
#pragma unroll
                for (int mt = 0; mt < 2; mt++)
                    mma_tf32(o[mt][nt], a[mt][0], a[mt][1], a[mt][2], a[mt][3], b0, b1);
            }
        }
    }

    // epilogue: finish deferred l-sum reduction, normalize, store
#pragma unroll
    for (int mt = 0; mt < 2; mt++) {
        float l0 = lr2[mt][0];
        l0 += __shfl_xor_sync(0xffffffffu, l0, 1);
        l0 += __shfl_xor_sync(0xffffffffu, l0, 2);
        float l1 = lr2[mt][1];
        l1 += __shfl_xor_sync(0xffffffffu, l1, 1);
        l1 += __shfl_xor_sync(0xffffffffu, l1, 2);
        float inv0 = 1.f / l0;
        float inv1 = 1.f / l1;
        int t0 = b * 128 + w * 32 + mt * 16 + gid;
        int t1 = t0 + 8;
#pragma unroll
        for (int nt = 0; nt < 8; nt++) {
            int col = h * DH + nt * 8 + tig * 2;
            float2 v0 = make_float2(o[mt][nt][0] * inv0, o[mt][nt][1] * inv0);
            *(float2*)(vals + (size_t)t0 * D + col) = v0;
            float2 v1 = make_float2(o[mt][nt][2] * inv1, o[mt][nt][3] * inv1);
            *(float2*)(vals + (size_t)t1 * D + col) = v1;
        }
    }
}

// ---------------------------------------------------------------------------
extern "C" void kernel_launch(void* const* d_in, const int* in_sizes, int n_in,
                              void* d_out, int out_size)
{
    const float* q     = (const float*)d_in[0];
    const float* k     = (const float*)d_in[1];
    const float* v     = (const float*)d_in[2];
    // d_in[3] = mask (causal tril, known statically — unused)
    const float* freqs = (const float*)d_in[4];
    const float* w_q   = (const float*)d_in[5];
    const float* w_k   = (const float*)d_in[6];
    const float* w_v   = (const float*)d_in[7];
    const float* w_o   = (const float*)d_in[8];
    float* out = (float*)d_out;

    float *Qh, *Kh, *Vh, *Vals;
    cudaGetSymbolAddress((void**)&Qh, g_Qh);
    cudaGetSymbolAddress((void**)&Kh, g_Kh);
    cudaGetSymbolAddress((void**)&Vh, g_Vh);
    cudaGetSymbolAddress((void**)&Vals, g_Vals);

    // merged q/k/v projections + RoPE  (block tile 128x128)
    proj_qkv_kernel<<<dim3(D / 128, T / 128, 3), 256>>>(
        q, k, v, w_q, w_k, w_v, freqs, Qh, Kh, Vh);

    // attention
    size_t smem = 25088 * sizeof(uint32_t);  // 100352 B
    cudaFuncSetAttribute(attn_kernel,
                         cudaFuncAttributeMaxDynamicSharedMemorySize, (int)smem);
    attn_kernel<<<dim3(T / 128, H), 128, smem>>>(Qh, Kh, Vh, Vals);

    // output projection
    proj_o_kernel<<<dim3(D / 128, T / 128), 256>>>(Vals, w_o, out);
}

// round 13
// speedup vs baseline: 1.4576x; 1.2200x over previous
#include <cuda_runtime.h>
#include <math.h>
#include <stdint.h>

#define T 4096
#define D 1024
#define H 16
#define DH 64
#define L 32

#define VSTR 72   // V smem row stride in words: 72 % 32 == 8 -> conflict-free scalar reads

// Scratch (allocation-free rule: __device__ globals)
__device__ float g_Qh[H * T * DH];
__device__ float g_Kh[H * T * DH];
__device__ float g_Vh[H * T * DH];
__device__ float g_Vals[T * D];

__device__ __forceinline__ uint32_t f2tf(float f) {
    uint32_t r;
    asm("cvt.rna.tf32.f32 %0, %1;" : "=r"(r) : "f"(f));
    return r;
}

__device__ __forceinline__ float ex2(float f) {
    float r;
    asm("ex2.approx.f32 %0, %1;" : "=f"(r) : "f"(f));
    return r;
}

__device__ __forceinline__ void mma_tf32(float c[4], uint32_t a0, uint32_t a1,
                                         uint32_t a2, uint32_t a3,
                                         uint32_t b0, uint32_t b1) {
    asm volatile(
        "mma.sync.aligned.m16n8k8.row.col.f32.tf32.tf32.f32 "
        "{%0,%1,%2,%3}, {%4,%5,%6,%7}, {%8,%9}, {%0,%1,%2,%3};\n"
        : "+f"(c[0]), "+f"(c[1]), "+f"(c[2]), "+f"(c[3])
        : "r"(a0), "r"(a1), "r"(a2), "r"(a3), "r"(b0), "r"(b1));
}

__device__ __forceinline__ void ldsm4(uint32_t& d0, uint32_t& d1, uint32_t& d2,
                                      uint32_t& d3, uint32_t saddr) {
    asm volatile(
        "ldmatrix.sync.aligned.m8n8.x4.shared.b16 {%0,%1,%2,%3}, [%4];"
        : "=r"(d0), "=r"(d1), "=r"(d2), "=r"(d3)
        : "r"(saddr));
}

// ---------------------------------------------------------------------------
// Projection GEMM (tf32 mma.sync + ldmatrix), double-buffered smem,
// ONE sync per k-block:  compute(kk) -> STS(kk+1, other buf) -> LDG(kk+2) -> sync
// out = X[M,K] @ W[N,K]^T.  Block tile 128x128, BK=32. 256 threads = 8 warps.
// smem (dynamic, 64KB): As0 As1 Bs0 Bs1, 16KB each.
// mode 0: row-major out [T,1024].
// mode 1: RoPE + head-major out [H][T][DH]; bx covers heads 2bx, 2bx+1.
// ---------------------------------------------------------------------------
__device__ __forceinline__ void proj_body(
    uint32_t* psm,
    const float* __restrict__ X, const float* __restrict__ W,
    const float* __restrict__ freqs, float* __restrict__ out, int mode,
    int bx, int by)
{
    uint32_t* Asb = psm;          // [2][4096] words
    uint32_t* Bsb = psm + 8192;   // [2][4096] words

    const int tid = threadIdx.x;
    const int lane = tid & 31;
    const int w = tid >> 5;
    const int gid = lane >> 2;
    const int tig = lane & 3;
    const int wm = w >> 1;
    const int wn = w & 1;

    const int lsub = lane >> 3;
    const int lr = lane & 7;
    const int khA = lsub >> 1;
    const int khB = lsub & 1;

    const uint32_t as_s = (uint32_t)__cvta_generic_to_shared(Asb);
    const uint32_t bs_s = (uint32_t)__cvta_generic_to_shared(Bsb);

    uint32_t aA[2];
#pragma unroll
    for (int mt = 0; mt < 2; mt++) {
        int rowA = wm * 32 + mt * 16 + lr + ((lsub & 1) << 3);
        aA[mt] = as_s + rowA * 128;
    }
    uint32_t bB[4];
#pragma unroll
    for (int np = 0; np < 4; np++) {
        int n = wn * 64 + np * 16 + lr + ((lsub >> 1) << 3);
        bB[np] = bs_s + n * 128;
    }

    float acc[2][8][4];
#pragma unroll
    for (int mt = 0; mt < 2; mt++)
#pragma unroll
        for (int nt = 0; nt < 8; nt++)
#pragma unroll
            for (int r = 0; r < 4; r++) acc[mt][nt][r] = 0.f;

    int rows_[4], kgs_[4], soff_[4];
#pragma unroll
    for (int i = 0; i < 4; i++) {
        int f = tid + i * 256;
        rows_[i] = f >> 3;
        kgs_[i] = f & 7;
        soff_[i] = rows_[i] * 32 + ((kgs_[i] ^ (rows_[i] & 7)) << 2);
    }

    const float* Xp = X + (size_t)(by * 128) * D;
    const float* Wp = W + (size_t)(bx * 128) * D;

    float4 ra[4], rb[4];
    // prologue: LDG k-block 0 -> STS buf0; LDG k-block 1 into regs; sync
#pragma unroll
    for (int i = 0; i < 4; i++) {
        ra[i] = *(const float4*)(Xp + (size_t)rows_[i] * D + kgs_[i] * 4);
        rb[i] = *(const float4*)(Wp + (size_t)rows_[i] * D + kgs_[i] * 4);
    }
#pragma unroll
    for (int i = 0; i < 4; i++) {
        uint4 ua = make_uint4(f2tf(ra[i].x), f2tf(ra[i].y), f2tf(ra[i].z), f2tf(ra[i].w));
        *(uint4*)&Asb[soff_[i]] = ua;
        uint4 ub = make_uint4(f2tf(rb[i].x), f2tf(rb[i].y), f2tf(rb[i].z), f2tf(rb[i].w));
        *(uint4*)&Bsb[soff_[i]] = ub;
    }
#pragma unroll
    for (int i = 0; i < 4; i++) {
        ra[i] = *(const float4*)(Xp + (size_t)rows_[i] * D + 32 + kgs_[i] * 4);
        rb[i] = *(const float4*)(Wp + (size_t)rows_[i] * D + 32 + kgs_[i] * 4);
    }
    __syncthreads();

    for (int kk = 0; kk < 32; kk++) {
        const uint32_t off = (uint32_t)(kk & 1) * 16384;   // bytes

        // compute from buf[cur]
#pragma unroll
        for (int ks = 0; ks < 4; ks++) {
            uint32_t a[2][4];
#pragma unroll
            for (int mt = 0; mt < 2; mt++)
                ldsm4(a[mt][0], a[mt][1], a[mt][2], a[mt][3],
                      aA[mt] + off + (((2 * ks + khA) ^ lr) << 4));
#pragma unroll
            for (int np = 0; np < 4; np++) {
                uint32_t b00, b01, b10, b11;
                ldsm4(b00, b01, b10, b11, bB[np] + off + (((2 * ks + khB) ^ lr) << 4));
#pragma unroll
                for (int mt = 0; mt < 2; mt++) {
                    mma_tf32(acc[mt][2 * np], a[mt][0], a[mt][1], a[mt][2], a[mt][3], b00, b01);
                    mma_tf32(acc[mt][2 * np + 1], a[mt][0], a[mt][1], a[mt][2], a[mt][3], b10, b11);
                }
            }
        }

        if (kk < 31) {
            // STS k-block kk+1 into the other buffer
            uint32_t* Ad = Asb + ((kk + 1) & 1) * 4096;
            uint32_t* Bd = Bsb + ((kk + 1) & 1) * 4096;
#pragma unroll
            for (int i = 0; i < 4; i++) {
                uint4 ua = make_uint4(f2tf(ra[i].x), f2tf(ra[i].y), f2tf(ra[i].z), f2tf(ra[i].w));
                *(uint4*)&Ad[soff_[i]] = ua;
                uint4 ub = make_uint4(f2tf(rb[i].x), f2tf(rb[i].y), f2tf(rb[i].z), f2tf(rb[i].w));
                *(uint4*)&Bd[soff_[i]] = ub;
            }
            if (kk < 30) {
                int k0 = (kk + 2) * 32;
#pragma unroll
                for (int i = 0; i < 4; i++) {
                    ra[i] = *(const float4*)(Xp + (size_t)rows_[i] * D + k0 + kgs_[i] * 4);
                    rb[i] = *(const float4*)(Wp + (size_t)rows_[i] * D + k0 + kgs_[i] * 4);
                }
            }
            __syncthreads();
        }
    }

    if (mode == 0) {
#pragma unroll
        for (int mt = 0; mt < 2; mt++) {
#pragma unroll
            for (int rh = 0; rh < 2; rh++) {
                int t = by * 128 + wm * 32 + mt * 16 + gid + rh * 8;
#pragma unroll
                for (int nt = 0; nt < 8; nt++) {
                    int col = bx * 128 + wn * 64 + nt * 8 + tig * 2;
                    float2 v = make_float2(acc[mt][nt][rh * 2], acc[mt][nt][rh * 2 + 1]);
                    *(float2*)(out + (size_t)t * D + col) = v;
                }
            }
        }
    } else {
        const int h = bx * 2 + wn;
#pragma unroll
        for (int mt = 0; mt < 2; mt++) {
#pragma unroll
            for (int rh = 0; rh < 2; rh++) {
                int t = by * 128 + wm * 32 + mt * 16 + gid + rh * 8;
                float* orow = out + (size_t)h * T * DH + (size_t)t * DH;
#pragma unroll
                for (int nt = 0; nt < 8; nt++) {
                    int c = nt * 8 + tig * 2;
                    if (nt < 4) {
                        float2 f2 = *(const float2*)(freqs + (size_t)t * L + c);
                        float x0 = acc[mt][nt][rh * 2];
                        float x1 = acc[mt][nt][rh * 2 + 1];
                        float p0 = acc[mt][nt ^ 2][rh * 2];
                        float p1 = acc[mt][nt ^ 2][rh * 2 + 1];
                        float r0 = (nt < 2) ? -p0 : p0;
                        float r1 = (nt < 2) ? -p1 : p1;
                        float2 v;
                        v.x = x0 * __cosf(f2.x) + r0 * __sinf(f2.x);
                        v.y = x1 * __cosf(f2.y) + r1 * __sinf(f2.y);
                        *(float2*)(orow + c) = v;
                    } else {
                        float2 v = make_float2(acc[mt][nt][rh * 2], acc[mt][nt][rh * 2 + 1]);
                        *(float2*)(orow + c) = v;
                    }
                }
            }
        }
    }
}

__global__ __launch_bounds__(256, 2) void proj_qkv_kernel(
    const float* __restrict__ q, const float* __restrict__ k,
    const float* __restrict__ v,
    const float* __restrict__ wq, const float* __restrict__ wk,
    const float* __restrict__ wv,
    const float* __restrict__ freqs,
    float* __restrict__ Qh, float* __restrict__ Kh, float* __restrict__ Vh)
{
    extern __shared__ uint32_t psm[];
    const int z = blockIdx.z;
    const float* X = (z == 0) ? q : (z == 1) ? k : v;
    const float* W = (z == 0) ? wq : (z == 1) ? wk : wv;
    float* out = (z == 0) ? Qh : (z == 1) ? Kh : Vh;
    proj_body(psm, X, W, freqs, out, 1, blockIdx.x, blockIdx.y);
}

__global__ __launch_bounds__(256, 2) void proj_o_kernel(
    const float* __restrict__ X, const float* __restrict__ W,
    float* __restrict__ out)
{
    extern __shared__ uint32_t psm[];
    proj_body(psm, X, W, nullptr, out, 0, blockIdx.x, blockIdx.y);
}

#define PJ_SMEM_BYTES 65536

// ---------------------------------------------------------------------------
// Causal flash attention, tf32 tensor cores + ldmatrix (R8/R12 layout).
// Flattened grid: bid -> (b = 31 - bid/16, h = bid%16) so the longest
// causal tiles launch first across ALL heads.
// ---------------------------------------------------------------------------
__global__ __launch_bounds__(128) void attn_kernel(
    const float* __restrict__ Q, const float* __restrict__ Kg,
    const float* __restrict__ Vg, float* __restrict__ vals)
{
    extern __shared__ uint32_t sm[];
    uint32_t* Qs = sm;                 // 128x64, xor-swizzled  (8192 w)
    uint32_t* Ks = sm + 8192;          // 64x64, xor-swizzled   (4096 w)
    uint32_t* Vs = sm + 12288;         // 64 rows x VSTR        (4608 w)
    uint32_t* Ps = sm + 16896;         // 128x64, xor-swizzled  (8192 w)
    // total 25088 w = 100352 B

    const int tid = threadIdx.x;
    const int lane = tid & 31;
    const int w = tid >> 5;
    const int gid = lane >> 2;
    const int tig = lane & 3;
    const int bid = blockIdx.x;
    const int b = 31 - (bid >> 4);     // long tiles first
    const int h = bid & 15;

    const int lsub = lane >> 3;
    const int lr = lane & 7;
    const int khA = lsub >> 1;
    const int khB = lsub & 1;

    const uint32_t qs_s = (uint32_t)__cvta_generic_to_shared(Qs);
    const uint32_t ks_s = (uint32_t)__cvta_generic_to_shared(Ks);
    const uint32_t ps_s = (uint32_t)__cvta_generic_to_shared(Ps);

    uint32_t aQ[2], aP[2];
#pragma unroll
    for (int mt = 0; mt < 2; mt++) {
        int rowA = w * 32 + mt * 16 + lr + ((lsub & 1) << 3);
        aQ[mt] = qs_s + rowA * 256;
        aP[mt] = ps_s + rowA * 256;
    }
    const int rowBr = lr + ((lsub >> 1) << 3);
    uint32_t bK[4];
#pragma unroll
    for (int np = 0; np < 4; np++)
        bK[np] = ks_s + (np * 16 + rowBr) * 256;

    const float* Qh = Q + (size_t)h * T * DH;
    const float* Kh = Kg + (size_t)h * T * DH;
    const float* Vh = Vg + (size_t)h * T * DH;

    // fill constants: per-thread base row/kgroup; swizzle term invariant in i
    const int m0 = tid >> 4;          // 0..7
    const int kg0 = tid & 15;
    const float* Kp = Kh + (size_t)m0 * DH + kg0 * 4;
    const float* Vp = Vh + (size_t)m0 * DH + kg0 * 4;
    uint32_t* ksw = &Ks[m0 * 64 + ((kg0 ^ (m0 & 7)) << 2)];   // +i*512
    uint32_t* vsw = &Vs[m0 * VSTR + kg0 * 4];                 // +i*8*VSTR

    // Q tile: prescale by 1/sqrt(DH)*log2(e), RNA tf32, swizzled
    const float qscale = 0.125f * 1.4426950408889634f;
#pragma unroll
    for (int i = 0; i < 16; i++) {
        int f = tid + i * 128;
        int m = f >> 4, kg = f & 15;
        float4 v4 = *(const float4*)(Qh + (size_t)(b * 128 + m) * DH + kg * 4);
        uint4 u = make_uint4(f2tf(v4.x * qscale), f2tf(v4.y * qscale),
                             f2tf(v4.z * qscale), f2tf(v4.w * qscale));
        *(uint4*)&Qs[m * 64 + ((kg ^ (m & 7)) << 2)] = u;
    }

    float o[2][8][4];
#pragma unroll
    for (int mt = 0; mt < 2; mt++)
#pragma unroll
        for (int nt = 0; nt < 8; nt++)
#pragma unroll
            for (int r = 0; r < 4; r++) o[mt][nt][r] = 0.f;
    float mr[2][2] = {{-1e30f, -1e30f}, {-1e30f, -1e30f}};
    float lr2[2][2] = {{0.f, 0.f}, {0.f, 0.f}};

    const int n_iters = 2 * b + 2;

    for (int jb = 0; jb < n_iters; jb++) {
        // prefetch K/V for this tile into registers BEFORE the barrier
        float4 kr[8], vr[8];
#pragma unroll
        for (int i = 0; i < 8; i++) {
            kr[i] = *(const float4*)(Kp + (size_t)i * 8 * DH);
            vr[i] = *(const float4*)(Vp + (size_t)i * 8 * DH);
        }
        Kp += (size_t)64 * DH;
        Vp += (size_t)64 * DH;

        __syncthreads();   // prior iter's K/V reads complete
#pragma unroll
        for (int i = 0; i < 8; i++) {
            uint4 uk = make_uint4(f2tf(kr[i].x), f2tf(kr[i].y), f2tf(kr[i].z), f2tf(kr[i].w));
            *(uint4*)(ksw + i * 512) = uk;
            uint4 uv = make_uint4(f2tf(vr[i].x), f2tf(vr[i].y), f2tf(vr[i].z), f2tf(vr[i].w));
            *(uint4*)(vsw + i * 8 * VSTR) = uv;
        }
        __syncthreads();

        // S = Q K^T  (32 x 64 per warp, B fragments reused across mt)
        float s[2][8][4];
#pragma unroll
        for (int mt = 0; mt < 2; mt++)
#pragma unroll
            for (int nt = 0; nt < 8; nt++)
#pragma unroll
                for (int r = 0; r < 4; r++) s[mt][nt][r] = 0.f;

#pragma unroll
        for (int ks = 0; ks < 8; ks++) {
            uint32_t a[2][4];
#pragma unroll
            for (int mt = 0; mt < 2; mt++)
                ldsm4(a[mt][0], a[mt][1], a[mt][2], a[mt][3],
                      aQ[mt] + (((2 * ks + khA) ^ lr) << 4));
#pragma unroll
            for (int np = 0; np < 4; np++) {
                uint32_t b00, b01, b10, b11;
                ldsm4(b00, b01, b10, b11, bK[np] + (((2 * ks + khB) ^ lr) << 4));
#pragma unroll
                for (int mt = 0; mt < 2; mt++) {
                    mma_tf32(s[mt][2 * np], a[mt][0], a[mt][1], a[mt][2], a[mt][3], b00, b01);
                    mma_tf32(s[mt][2 * np + 1], a[mt][0], a[mt][1], a[mt][2], a[mt][3], b10, b11);
                }
            }
        }

        // causal mask (only last two KV tiles cross the diagonal)
        if (jb >= 2 * b) {
#pragma unroll
            for (int mt = 0; mt < 2; mt++)
#pragma unroll
                for (int nt = 0; nt < 8; nt++)
#pragma unroll
                    for (int r = 0; r < 4; r++) {
                        int col = jb * 64 + nt * 8 + tig * 2 + (r & 1);
                        int row = b * 128 + w * 32 + mt * 16 + gid + ((r & 2) ? 8 : 0);
                        if (col > row) s[mt][nt][r] = -1e30f;
                    }
        }

        // online softmax (log2 domain; two rows per thread per mt)
#pragma unroll
        for (int mt = 0; mt < 2; mt++) {
#pragma unroll
            for (int half = 0; half < 2; half++) {
                float mx = -1e30f;
#pragma unroll
                for (int nt = 0; nt < 8; nt++) {
                    mx = fmaxf(mx, s[mt][nt][half * 2]);
                    mx = fmaxf(mx, s[mt][nt][half * 2 + 1]);
                }
                mx = fmaxf(mx, __shfl_xor_sync(0xffffffffu, mx, 1));
                mx = fmaxf(mx, __shfl_xor_sync(0xffffffffu, mx, 2));
                float mnew = fmaxf(mr[mt][half], mx);
                float alpha = ex2(mr[mt][half] - mnew);
                mr[mt][half] = mnew;
                float rs = 0.f;
#pragma unroll
                for (int nt = 0; nt < 8; nt++) {
                    float p0 = ex2(s[mt][nt][half * 2] - mnew);
                    float p1 = ex2(s[mt][nt][half * 2 + 1] - mnew);
                    s[mt][nt][half * 2] = p0;
                    s[mt][nt][half * 2 + 1] = p1;
                    rs += p0 + p1;
                }
                lr2[mt][half] = lr2[mt][half] * alpha + rs;
#pragma unroll
                for (int nt = 0; nt < 8; nt++) {
                    o[mt][nt][half * 2] *= alpha;
                    o[mt][nt][half * 2 + 1] *= alpha;
                }
            }

            // write P (RNA tf32) to warp-private smem rows
            int ra_ = w * 32 + mt * 16 + gid;
            int rb_ = ra_ + 8;
#pragma unroll
            for (int nt = 0; nt < 8; nt++) {
                int col = nt * 8 + tig * 2;
                uint2 p01 = make_uint2(f2tf(s[mt][nt][0]), f2tf(s[mt][nt][1]));
                *(uint2*)&Ps[ra_ * 64 + (col ^ ((ra_ & 7) << 2))] = p01;
                uint2 p23 = make_uint2(f2tf(s[mt][nt][2]), f2tf(s[mt][nt][3]));
                *(uint2*)&Ps[rb_ * 64 + (col ^ ((rb_ & 7) << 2))] = p23;
            }
        }
        __syncwarp();

        // O += P V  (P via ldmatrix; V scalar, stride-72 conflict-free;
        //            V fragments reused across mt)
#pragma unroll
        for (int ks = 0; ks < 8; ks++) {
            int kb = ks * 8;
            uint32_t a[2][4];
#pragma unroll
            for (int mt = 0; mt < 2; mt++)
                ldsm4(a[mt][0], a[mt][1], a[mt][2], a[mt][3],
                      aP[mt] + (((2 * ks + khA) ^ lr) << 4));
            int kr0 = kb + tig, kr1 = kb + tig + 4;
            const uint32_t* vrow0 = Vs + kr0 * VSTR + gid;
            const uint32_t* vrow1 = Vs + kr1 * VSTR + gid;
#pragma unroll
            for (int nt = 0; nt < 8; nt++) {
                uint32_t b0 = vrow0[nt * 8];
                uint32_t b1 = vrow1[nt * 8];
#pragma unroll
                for (int mt = 0; mt < 2; mt++)
                    mma_tf32(o[mt][nt], a[mt][0], a[mt][1], a[mt][2], a[mt][3], b0, b1);
            }
        }
    }

    // epilogue: finish deferred l-sum reduction, normalize, store
#pragma unroll
    for (int mt = 0; mt < 2; mt++) {
        float l0 = lr2[mt][0];
        l0 += __shfl_xor_sync(0xffffffffu, l0, 1);
        l0 += __shfl_xor_sync(0xffffffffu, l0, 2);
        float l1 = lr2[mt][1];
        l1 += __shfl_xor_sync(0xffffffffu, l1, 1);
        l1 += __shfl_xor_sync(0xffffffffu, l1, 2);
        float inv0 = 1.f / l0;
        float inv1 = 1.f / l1;
        int t0 = b * 128 + w * 32 + mt * 16 + gid;
        int t1 = t0 + 8;
#pragma unroll
        for (int nt = 0; nt < 8; nt++) {
            int col = h * DH + nt * 8 + tig * 2;
            float2 v0 = make_float2(o[mt][nt][0] * inv0, o[mt][nt][1] * inv0);
            *(float2*)(vals + (size_t)t0 * D + col) = v0;
            float2 v1 = make_float2(o[mt][nt][2] * inv1, o[mt][nt][3] * inv1);
            *(float2*)(vals + (size_t)t1 * D + col) = v1;
        }
    }
}

// ---------------------------------------------------------------------------
extern "C" void kernel_launch(void* const* d_in, const int* in_sizes, int n_in,
                              void* d_out, int out_size)
{
    const float* q     = (const float*)d_in[0];
    const float* k     = (const float*)d_in[1];
    const float* v     = (const float*)d_in[2];
    // d_in[3] = mask (causal tril, known statically — unused)
    const float* freqs = (const float*)d_in[4];
    const float* w_q   = (const float*)d_in[5];
    const float* w_k   = (const float*)d_in[6];
    const float* w_v   = (const float*)d_in[7];
    const float* w_o   = (const float*)d_in[8];
    float* out = (float*)d_out;

    float *Qh, *Kh, *Vh, *Vals;
    cudaGetSymbolAddress((void**)&Qh, g_Qh);
    cudaGetSymbolAddress((void**)&Kh, g_Kh);
    cudaGetSymbolAddress((void**)&Vh, g_Vh);
    cudaGetSymbolAddress((void**)&Vals, g_Vals);

    cudaFuncSetAttribute(proj_qkv_kernel,
                         cudaFuncAttributeMaxDynamicSharedMemorySize, PJ_SMEM_BYTES);
    cudaFuncSetAttribute(proj_o_kernel,
                         cudaFuncAttributeMaxDynamicSharedMemorySize, PJ_SMEM_BYTES);

    // merged q/k/v projections + RoPE  (block tile 128x128, double-buffered)
    proj_qkv_kernel<<<dim3(D / 128, T / 128, 3), 256, PJ_SMEM_BYTES>>>(
        q, k, v, w_q, w_k, w_v, freqs, Qh, Kh, Vh);

    // attention (flattened longest-first grid)
    size_t smem = 25088 * sizeof(uint32_t);  // 100352 B
    cudaFuncSetAttribute(attn_kernel,
                         cudaFuncAttributeMaxDynamicSharedMemorySize, (int)smem);
    attn_kernel<<<dim3((T / 128) * H), 128, smem>>>(Qh, Kh, Vh, Vals);

    // output projection
    proj_o_kernel<<<dim3(D / 128, T / 128), 256, PJ_SMEM_BYTES>>>(Vals, w_o, out);
}